// round 10
// baseline (speedup 1.0000x reference)
#include <cuda_runtime.h>
#include <cuda_fp16.h>
#include <cstdint>
#include <math.h>

static constexpr int Bz  = 4096;
static constexpr int Ls  = 10;
static constexpr int IND = 8;
static constexpr int Hd  = 512;
static constexpr int Gd  = 1536;   // 3*Hd

// ---------------- scratch (offsets in float units; fp16 buffers take half) ----------------
static constexpr size_t OFF_XG_DEC  = 0;                                      // Bz*Gd fp16
static constexpr size_t OFF_HG      = OFF_XG_DEC  + (size_t)Bz*Gd/2;          // Bz*Gd fp16
static constexpr size_t OFF_ENC1    = OFF_HG      + (size_t)Bz*Gd/2;          // Ls*Bz*Hd fp16
static constexpr size_t OFF_ENC_W3  = OFF_ENC1    + (size_t)Ls*Bz*Hd/2;       // Ls*Bz*Hd fp16
static constexpr size_t OFF_H1_ALL  = OFF_ENC_W3  + (size_t)Ls*Bz*Hd/2;       // Ls*Bz*Hd fp16
static constexpr size_t OFF_A_ALL   = OFF_H1_ALL  + (size_t)Ls*Bz*Hd/2;       // Ls*Bz*Hd fp16
static constexpr size_t OFF_DEC1    = OFF_A_ALL   + (size_t)Ls*Bz*Hd/2;       // Bz*Hd fp16
static constexpr size_t OFF_WHHE1   = OFF_DEC1    + (size_t)Bz*Hd/2;          // Gd*Hd fp16
static constexpr size_t OFF_WHHD1   = OFF_WHHE1   + (size_t)Gd*Hd/2;
static constexpr size_t OFF_WIHD1   = OFF_WHHD1   + (size_t)Gd*Hd/2;
static constexpr size_t OFF_W31     = OFF_WIHD1   + (size_t)Gd*Hd/2;          // Hd*Hd fp16
static constexpr size_t OFF_W41     = OFF_W31     + (size_t)Hd*Hd/2;
static constexpr size_t OFF_CW      = OFF_W41     + (size_t)Hd*Hd/2;          // Gd*IND f32
static constexpr size_t OFF_CB      = OFF_CW      + (size_t)Gd*IND;           // Gd f32
static constexpr size_t SCRATCH_TOTAL = OFF_CB + Gd;

__device__ __align__(1024) float g_scratch[SCRATCH_TOTAL];

// ---------------- math helpers ----------------
__device__ __forceinline__ float sigm_f(float x) { return 1.0f / (1.0f + __expf(-x)); }
__device__ __forceinline__ float tanh_f(float x) {
    float ax = fabsf(x);
    float t  = __expf(-2.0f * ax);
    float r  = __fdividef(1.0f - t, 1.0f + t);
    return copysignf(r, x);
}

// ---------------- PTX helpers ----------------
__device__ __forceinline__ uint32_t smem_u32(const void* p) {
    uint32_t a;
    asm("{ .reg .u64 t; cvta.to.shared.u64 t, %1; cvt.u32.u64 %0, t; }" : "=r"(a) : "l"(p));
    return a;
}
__device__ __forceinline__ void cp16(uint32_t s, const void* g) {
    asm volatile("cp.async.cg.shared.global [%0], [%1], 16;" :: "r"(s), "l"(g) : "memory");
}
__device__ __forceinline__ void ldm_x4(uint32_t& r0, uint32_t& r1, uint32_t& r2, uint32_t& r3,
                                       uint32_t addr) {
    asm volatile("ldmatrix.sync.aligned.m8n8.x4.shared.b16 {%0,%1,%2,%3}, [%4];"
                 : "=r"(r0), "=r"(r1), "=r"(r2), "=r"(r3) : "r"(addr));
}
__device__ __forceinline__ void mma16816(float* c, const uint32_t* a, uint32_t b0, uint32_t b1) {
    asm volatile("mma.sync.aligned.m16n8k16.row.col.f32.f16.f16.f32 "
                 "{%0,%1,%2,%3}, {%4,%5,%6,%7}, {%8,%9}, {%0,%1,%2,%3};"
                 : "+f"(c[0]), "+f"(c[1]), "+f"(c[2]), "+f"(c[3])
                 : "r"(a[0]), "r"(a[1]), "r"(a[2]), "r"(a[3]), "r"(b0), "r"(b1));
}

static constexpr int AB_STRIDE = 10240;   // 128 rows * 80 B

// ---------------- fp16 tensor-core GEMM: C[M,N] (fp16) = A @ W^T (+f32 bias) ----------------
// A1[M,512], W1[N,512] fp16. 16 K-tiles of 32, 2-stage cp.async double buffer.
// 128x128 CTA tile, 256 threads (8 warps of 32x64). 80-byte smem rows (conflict-free).
__global__ void __launch_bounds__(256, 2) k_gemm_mma(
    const __half* __restrict__ A1, const __half* __restrict__ W1,
    const float* __restrict__ bias, __half* __restrict__ C, int N)
{
    __shared__ __half As[2][128][40];
    __shared__ __half Bs[2][128][40];
    const int tid  = threadIdx.x;
    const int wid  = tid >> 5, lane = tid & 31;
    const int wm   = wid & 3;
    const int wn   = wid >> 2;
    const size_t bm = (size_t)blockIdx.x * 128;
    const size_t bn = (size_t)blockIdx.y * 128;

    const uint32_t sA = smem_u32(As);
    const uint32_t sB = smem_u32(Bs);

    float acc[2][8][4];
#pragma unroll
    for (int i = 0; i < 2; i++)
#pragma unroll
        for (int j = 0; j < 8; j++)
#pragma unroll
            for (int q = 0; q < 4; q++) acc[i][j][q] = 0.0f;

    const int lrow = tid >> 2;             // 0..63
    const int lcol = (tid & 3) << 4;       // byte 0,16,32,48
    const char* aG = (const char*)A1 + (bm + lrow) * 1024 + lcol;
    const char* bG = (const char*)W1 + (bn + lrow) * 1024 + lcol;
    const uint32_t dA = sA + lrow * 80 + lcol;
    const uint32_t dB = sB + lrow * 80 + lcol;

#define LOAD_TILE(kt, buf)                                                \
    {                                                                     \
        int ko_ = (kt) * 64;                                              \
        cp16(dA + (buf) * AB_STRIDE,           aG + ko_);                 \
        cp16(dA + (buf) * AB_STRIDE + 64 * 80, aG + 64 * 1024 + ko_);     \
        cp16(dB + (buf) * AB_STRIDE,           bG + ko_);                 \
        cp16(dB + (buf) * AB_STRIDE + 64 * 80, bG + 64 * 1024 + ko_);     \
        asm volatile("cp.async.commit_group;" ::: "memory");              \
    }

    LOAD_TILE(0, 0);

    const uint32_t mA0 = sA + (wm * 32 + (lane & 15)) * 80 + ((lane >> 4) << 4);
    const uint32_t mB0 = sB + (wn * 64 + (lane & 15)) * 80 + ((lane >> 4) << 4);

    for (int kt = 0; kt < 16; kt++) {
        int buf = kt & 1;
        if (kt < 15) {
            LOAD_TILE(kt + 1, buf ^ 1);
            asm volatile("cp.async.wait_group 1;" ::: "memory");
        } else {
            asm volatile("cp.async.wait_group 0;" ::: "memory");
        }
        __syncthreads();

#pragma unroll
        for (int ks = 0; ks < 2; ks++) {
            uint32_t a[2][4], b[4][4];
#pragma unroll
            for (int mf = 0; mf < 2; mf++)
                ldm_x4(a[mf][0], a[mf][1], a[mf][2], a[mf][3],
                       mA0 + buf * AB_STRIDE + mf * 16 * 80 + ks * 32);
#pragma unroll
            for (int nb = 0; nb < 4; nb++)
                ldm_x4(b[nb][0], b[nb][1], b[nb][2], b[nb][3],
                       mB0 + buf * AB_STRIDE + nb * 16 * 80 + ks * 32);
#pragma unroll
            for (int mf = 0; mf < 2; mf++)
#pragma unroll
                for (int nb = 0; nb < 4; nb++) {
                    mma16816(acc[mf][2 * nb + 0], a[mf], b[nb][0], b[nb][2]);
                    mma16816(acc[mf][2 * nb + 1], a[mf], b[nb][1], b[nb][3]);
                }
        }
        __syncthreads();
    }
#undef LOAD_TILE

#pragma unroll
    for (int mf = 0; mf < 2; mf++) {
#pragma unroll
        for (int nf = 0; nf < 8; nf++) {
            size_t r0 = bm + wm * 32 + mf * 16 + (lane >> 2);
            int    c0 = (int)bn + wn * 64 + nf * 8 + (lane & 3) * 2;
            float bv0 = 0.f, bv1 = 0.f;
            if (bias) { bv0 = bias[c0]; bv1 = bias[c0 + 1]; }
            *reinterpret_cast<__half2*>(&C[r0 * (size_t)N + c0]) =
                __floats2half2_rn(acc[mf][nf][0] + bv0, acc[mf][nf][1] + bv1);
            *reinterpret_cast<__half2*>(&C[(r0 + 8) * (size_t)N + c0]) =
                __floats2half2_rn(acc[mf][nf][2] + bv0, acc[mf][nf][3] + bv1);
        }
    }
}

// ---------------- one-shot cast of all weights + decoder input ----------------
static constexpr size_t CN0 = (size_t)Gd * Hd;          // enc_whh
static constexpr size_t CN1 = CN0 + (size_t)Gd * Hd;    // dec_whh
static constexpr size_t CN2 = CN1 + (size_t)Gd * Hd;    // dec_wih
static constexpr size_t CN3 = CN2 + (size_t)Hd * Hd;    // w3
static constexpr size_t CN4 = CN3 + (size_t)Hd * Hd;    // w4
static constexpr size_t CN5 = CN4 + (size_t)Bz * Hd;    // dec_in

__global__ void k_cast_all(const float* __restrict__ a0, const float* __restrict__ a1,
                           const float* __restrict__ a2, const float* __restrict__ a3,
                           const float* __restrict__ a4, const float* __restrict__ a5,
                           __half* __restrict__ b0, __half* __restrict__ b1,
                           __half* __restrict__ b2, __half* __restrict__ b3,
                           __half* __restrict__ b4, __half* __restrict__ b5)
{
    size_t idx = (size_t)blockIdx.x * blockDim.x + threadIdx.x;
    if      (idx < CN0) b0[idx]       = __float2half(a0[idx]);
    else if (idx < CN1) b1[idx - CN0] = __float2half(a1[idx - CN0]);
    else if (idx < CN2) b2[idx - CN1] = __float2half(a2[idx - CN1]);
    else if (idx < CN3) b3[idx - CN2] = __float2half(a3[idx - CN2]);
    else if (idx < CN4) b4[idx - CN3] = __float2half(a4[idx - CN3]);
    else if (idx < CN5) b5[idx - CN4] = __float2half(a5[idx - CN4]);
}

// ---------------- combine: cw = enc_wih @ emb_w, cb = enc_wih@emb_b + enc_bih ----------------
__global__ void k_combine(const float* __restrict__ enc_wih, const float* __restrict__ emb_w,
                          const float* __restrict__ emb_b,  const float* __restrict__ enc_bih,
                          float* __restrict__ cw, float* __restrict__ cb)
{
    int g = blockIdx.x, tid = threadIdx.x;
    float p[IND + 1];
#pragma unroll
    for (int i = 0; i <= IND; i++) p[i] = 0.0f;
    const float* wr = enc_wih + (size_t)g * Hd;
    for (int k = tid; k < Hd; k += 128) {
        float wv = wr[k];
#pragma unroll
        for (int i = 0; i < IND; i++) p[i] += wv * emb_w[(size_t)k * IND + i];
        p[IND] += wv * emb_b[k];
    }
#pragma unroll
    for (int i = 0; i <= IND; i++)
        for (int o = 16; o; o >>= 1) p[i] += __shfl_xor_sync(0xffffffffu, p[i], o);
    __shared__ float red[IND + 1][4];
    int wid = tid >> 5, lane = tid & 31;
    if (!lane)
#pragma unroll
        for (int i = 0; i <= IND; i++) red[i][wid] = p[i];
    __syncthreads();
    if (tid <= IND) {
        float s = red[tid][0] + red[tid][1] + red[tid][2] + red[tid][3];
        if (tid < IND) cw[(size_t)g * IND + tid] = s;
        else           cb[g] = s + enc_bih[g];
    }
}

// ---------------- encoder GRU gate (fp16 hg/hprev, inline input-gate dots) ----------------
__global__ void k_gate_enc(const float* __restrict__ items, int t,
                           const float* __restrict__ cw, const float* __restrict__ cb,
                           const __half2* __restrict__ hg, const float* __restrict__ bhh,
                           const __half2* __restrict__ hprev, __half2* __restrict__ h1)
{
    int idx = blockIdx.x * blockDim.x + threadIdx.x;   // Bz * 256
    int b = idx >> 8, q = idx & 255;
    int j0 = q * 2, j1 = j0 + 1;
    const float4* it = reinterpret_cast<const float4*>(items + ((size_t)b * Ls + t) * IND);
    float4 i0 = it[0], i1 = it[1];
    auto xdot = [&](int g) {
        const float4* w = reinterpret_cast<const float4*>(cw + (size_t)g * IND);
        float4 w0 = w[0], w1 = w[1];
        return cb[g]
            + i0.x * w0.x + i0.y * w0.y + i0.z * w0.z + i0.w * w0.w
            + i1.x * w1.x + i1.y * w1.y + i1.z * w1.z + i1.w * w1.w;
    };
    float xr0 = xdot(j0),          xr1 = xdot(j1);
    float xz0 = xdot(Hd + j0),     xz1 = xdot(Hd + j1);
    float xn0 = xdot(2 * Hd + j0), xn1 = xdot(2 * Hd + j1);

    float hr0, hr1, hz0, hz1, hn0, hn1;
    if (hg) {
        const __half2* g = hg + (size_t)b * 768;
        float2 v;
        v = __half22float2(g[q]);       hr0 = v.x; hr1 = v.y;
        v = __half22float2(g[256 + q]); hz0 = v.x; hz1 = v.y;
        v = __half22float2(g[512 + q]); hn0 = v.x; hn1 = v.y;
    } else {
        hr0 = bhh[j0];          hr1 = bhh[j1];
        hz0 = bhh[Hd + j0];     hz1 = bhh[Hd + j1];
        hn0 = bhh[2 * Hd + j0]; hn1 = bhh[2 * Hd + j1];
    }
    float hp0 = 0.f, hp1 = 0.f;
    if (hprev) {
        float2 v = __half22float2(hprev[(size_t)b * 256 + q]);
        hp0 = v.x; hp1 = v.y;
    }
    float r0 = sigm_f(xr0 + hr0), r1 = sigm_f(xr1 + hr1);
    float z0 = sigm_f(xz0 + hz0), z1 = sigm_f(xz1 + hz1);
    float n0 = tanh_f(xn0 + r0 * hn0), n1 = tanh_f(xn1 + r1 * hn1);
    h1[(size_t)b * 256 + q] =
        __floats2half2_rn(n0 + z0 * (hp0 - n0), n1 + z1 * (hp1 - n1));
}

// ---------------- decoder GRU gate (all fp16 I/O) ----------------
__global__ void k_gate_dec(const __half2* __restrict__ xg, const __half2* __restrict__ hg,
                           const __half2* __restrict__ hprev, __half2* __restrict__ h1)
{
    int idx = blockIdx.x * blockDim.x + threadIdx.x;   // Bz * 256
    int b = idx >> 8, q = idx & 255;
    const __half2* x = xg + (size_t)b * 768;
    const __half2* g = hg + (size_t)b * 768;
    float2 xr = __half22float2(x[q]);
    float2 xz = __half22float2(x[256 + q]);
    float2 xn = __half22float2(x[512 + q]);
    float2 hr = __half22float2(g[q]);
    float2 hz = __half22float2(g[256 + q]);
    float2 hn = __half22float2(g[512 + q]);
    float2 hp = __half22float2(hprev[(size_t)b * 256 + q]);
    float r0 = sigm_f(xr.x + hr.x), r1 = sigm_f(xr.y + hr.y);
    float z0 = sigm_f(xz.x + hz.x), z1 = sigm_f(xz.y + hz.y);
    float n0 = tanh_f(xn.x + r0 * hn.x), n1 = tanh_f(xn.y + r1 * hn.y);
    h1[(size_t)b * 256 + q] =
        __floats2half2_rn(n0 + z0 * (hp.x - n0), n1 + z1 * (hp.y - n1));
}

// ---------------- batched out_seq over all (t, l): one block per b ----------------
__global__ void __launch_bounds__(256) k_seq_all(
    const __half* __restrict__ encw3, const __half* __restrict__ A_all,
    const float* __restrict__ v2, float* __restrict__ out)
{
    int b = blockIdx.x, tid = threadIdx.x;
    int wid = tid >> 5, lane = tid & 31;
    __shared__ float Ash[Ls][Hd];
    __shared__ float v2s[Hd];
    __shared__ float red[8][Ls];
    for (int i = tid; i < Hd; i += 256) v2s[i] = v2[i];
    for (int t = 0; t < Ls; t++)
        for (int i = tid; i < Hd; i += 256)
            Ash[t][i] = __half2float(A_all[((size_t)t * Bz + b) * Hd + i]);
    __syncthreads();

    for (int l = 0; l < Ls; l++) {
        const __half* e = encw3 + ((size_t)l * Bz + b) * Hd;
        float s[Ls];
#pragma unroll
        for (int t = 0; t < Ls; t++) s[t] = 0.0f;
#pragma unroll
        for (int it = 0; it < 2; it++) {
            int k = tid + it * 256;
            float ek = __half2float(e[k]), vk = v2s[k];
#pragma unroll
            for (int t = 0; t < Ls; t++) s[t] += vk * tanh_f(ek + Ash[t][k]);
        }
#pragma unroll
        for (int t = 0; t < Ls; t++)
            for (int o = 16; o; o >>= 1) s[t] += __shfl_xor_sync(0xffffffffu, s[t], o);
        if (!lane)
#pragma unroll
            for (int t = 0; t < Ls; t++) red[wid][t] = s[t];
        __syncthreads();
        if (tid < Ls) {
            float tot = 0.0f;
#pragma unroll
            for (int w = 0; w < 8; w++) tot += red[w][tid];
            out[((size_t)b * Ls + tid) * Ls + l] = tot;
        }
        __syncthreads();
    }
}

// ---------------- batched out_ori: one warp per (t, b), fp16 h ----------------
__global__ void k_ori_all(const __half* __restrict__ H1_all, const float* __restrict__ wori,
                          const float* __restrict__ bori, float* __restrict__ out)
{
    int gw   = (blockIdx.x * blockDim.x + threadIdx.x) >> 5;  // t*Bz + b
    int lane = threadIdx.x & 31;
    int t = gw >> 12, b = gw & 4095;
    float s[6] = {0, 0, 0, 0, 0, 0};
    const __half* hb = H1_all + ((size_t)t * Bz + b) * Hd;
    for (int k = lane; k < Hd; k += 32) {
        float hv = __half2float(hb[k]);
#pragma unroll
        for (int j = 0; j < 6; j++) s[j] += hv * wori[(size_t)j * Gd + Hd + k];
    }
#pragma unroll
    for (int j = 0; j < 6; j++)
        for (int o = 16; o; o >>= 1) s[j] += __shfl_xor_sync(0xffffffffu, s[j], o);
    if (!lane)
#pragma unroll
        for (int j = 0; j < 6; j++)
            out[((size_t)b * Ls + t) * 6 + j] = s[j] + bori[j];
}

// ---------------- launch ----------------
extern "C" void kernel_launch(void* const* d_in, const int* in_sizes, int n_in,
                              void* d_out, int out_size)
{
    const float* items    = (const float*)d_in[0];
    const float* dec_in   = (const float*)d_in[1];
    const float* emb_w    = (const float*)d_in[2];
    const float* emb_b    = (const float*)d_in[3];
    const float* enc_wih  = (const float*)d_in[4];
    const float* enc_whh  = (const float*)d_in[5];
    const float* enc_bih  = (const float*)d_in[6];
    const float* enc_bhh  = (const float*)d_in[7];
    const float* dec_wih  = (const float*)d_in[8];
    const float* dec_whh  = (const float*)d_in[9];
    const float* dec_bih  = (const float*)d_in[10];
    const float* dec_bhh  = (const float*)d_in[11];
    const float* w3       = (const float*)d_in[14];
    const float* w4       = (const float*)d_in[15];
    const float* v2       = (const float*)d_in[20];
    const float* wori     = (const float*)d_in[23];
    const float* bori     = (const float*)d_in[24];

    float* out_seq = (float*)d_out;                        // (Bz, Ls, Ls)
    float* out_ori = (float*)d_out + (size_t)Bz * Ls * Ls; // (Bz, Ls, 6)

    float* S = nullptr;
    cudaGetSymbolAddress((void**)&S, g_scratch);
    float* CW      = S + OFF_CW;
    float* CB      = S + OFF_CB;
    __half* XG_DEC = (__half*)(S + OFF_XG_DEC);
    __half* HG     = (__half*)(S + OFF_HG);
    __half* ENC1   = (__half*)(S + OFF_ENC1);
    __half* ENC_W3 = (__half*)(S + OFF_ENC_W3);
    __half* H1_ALL = (__half*)(S + OFF_H1_ALL);
    __half* A_ALL  = (__half*)(S + OFF_A_ALL);
    __half* DEC1   = (__half*)(S + OFF_DEC1);
    __half* WHHE1  = (__half*)(S + OFF_WHHE1);
    __half* WHHD1  = (__half*)(S + OFF_WHHD1);
    __half* WIHD1  = (__half*)(S + OFF_WIHD1);
    __half* W31    = (__half*)(S + OFF_W31);
    __half* W41    = (__half*)(S + OFF_W41);

    // all casts in one launch
    k_cast_all<<<(unsigned)(CN5 / 256), 256>>>(enc_whh, dec_whh, dec_wih, w3, w4, dec_in,
                                               WHHE1, WHHD1, WIHD1, W31, W41, DEC1);

    // combined encoder input weights
    k_combine<<<Gd, 128>>>(enc_wih, emb_w, emb_b, enc_bih, CW, CB);

    // decoder input gates (step-invariant)
    k_gemm_mma<<<dim3(Bz / 128, Gd / 128), 256>>>(DEC1, WIHD1, dec_bih, XG_DEC, Gd);

    // encoder GRU scan
    for (int t = 0; t < Ls; t++) {
        const __half2* hp1 = t ? (__half2*)(ENC1 + (size_t)(t - 1) * Bz * Hd) : nullptr;
        if (t)
            k_gemm_mma<<<dim3(Bz / 128, Gd / 128), 256>>>(
                ENC1 + (size_t)(t - 1) * Bz * Hd, WHHE1, enc_bhh, HG, Gd);
        k_gate_enc<<<(Bz * 256) / 256, 256>>>(items, t, CW, CB,
                                              t ? (__half2*)HG : nullptr, enc_bhh, hp1,
                                              (__half2*)(ENC1 + (size_t)t * Bz * Hd));
    }

    // enc_w3 = enc_out @ w3^T  (all Ls*Bz rows batched)
    k_gemm_mma<<<dim3((Ls * Bz) / 128, Hd / 128), 256>>>(ENC1, W31, nullptr, ENC_W3, Hd);

    // decoder scan (w4 GEMM batched after)
    const __half* hp1 = ENC1 + (size_t)(Ls - 1) * Bz * Hd;
    for (int t = 0; t < Ls; t++) {
        __half* ht1 = H1_ALL + (size_t)t * Bz * Hd;
        k_gemm_mma<<<dim3(Bz / 128, Gd / 128), 256>>>(hp1, WHHD1, dec_bhh, HG, Gd);
        k_gate_dec<<<(Bz * 256) / 256, 256>>>((const __half2*)XG_DEC, (const __half2*)HG,
                                              (const __half2*)hp1, (__half2*)ht1);
        hp1 = ht1;
    }

    // A_ALL = H1_ALL @ w4^T  (all Ls*Bz rows batched)
    k_gemm_mma<<<dim3((Ls * Bz) / 128, Hd / 128), 256>>>(H1_ALL, W41, nullptr, A_ALL, Hd);

    // batched epilogues
    k_seq_all<<<Bz, 256>>>(ENC_W3, A_ALL, v2, out_seq);
    k_ori_all<<<(Bz * Ls) / 8, 256>>>(H1_ALL, wori, bori, out_ori);
}

// round 11
// speedup vs baseline: 1.1254x; 1.1254x over previous
#include <cuda_runtime.h>
#include <cuda_fp16.h>
#include <cstdint>
#include <math.h>

static constexpr int Bz  = 4096;
static constexpr int Ls  = 10;
static constexpr int IND = 8;
static constexpr int Hd  = 512;
static constexpr int Gd  = 1536;   // 3*Hd

// ---------------- scratch (offsets in float units; fp16 buffers take half) ----------------
static constexpr size_t OFF_XG_DEC  = 0;                                      // Bz*Gd fp16
static constexpr size_t OFF_HG      = OFF_XG_DEC  + (size_t)Bz*Gd/2;          // Bz*Gd fp16
static constexpr size_t OFF_XG_ENC  = OFF_HG      + (size_t)Bz*Gd/2;          // Ls*Bz*Gd fp16
static constexpr size_t OFF_ENC1    = OFF_XG_ENC  + (size_t)Ls*Bz*Gd/2;       // Ls*Bz*Hd fp16
static constexpr size_t OFF_ENC_W3  = OFF_ENC1    + (size_t)Ls*Bz*Hd/2;       // Ls*Bz*Hd fp16
static constexpr size_t OFF_H1_ALL  = OFF_ENC_W3  + (size_t)Ls*Bz*Hd/2;       // Ls*Bz*Hd fp16
static constexpr size_t OFF_A_ALL   = OFF_H1_ALL  + (size_t)Ls*Bz*Hd/2;       // Ls*Bz*Hd fp16
static constexpr size_t OFF_DEC1    = OFF_A_ALL   + (size_t)Ls*Bz*Hd/2;       // Bz*Hd fp16
static constexpr size_t OFF_WHHE1   = OFF_DEC1    + (size_t)Bz*Hd/2;          // Gd*Hd fp16
static constexpr size_t OFF_WHHD1   = OFF_WHHE1   + (size_t)Gd*Hd/2;
static constexpr size_t OFF_WIHD1   = OFF_WHHD1   + (size_t)Gd*Hd/2;
static constexpr size_t OFF_W31     = OFF_WIHD1   + (size_t)Gd*Hd/2;          // Hd*Hd fp16
static constexpr size_t OFF_W41     = OFF_W31     + (size_t)Hd*Hd/2;
static constexpr size_t OFF_CW      = OFF_W41     + (size_t)Hd*Hd/2;          // Gd*IND f32
static constexpr size_t OFF_CB      = OFF_CW      + (size_t)Gd*IND;           // Gd f32
static constexpr size_t SCRATCH_TOTAL = OFF_CB + Gd;

__device__ __align__(1024) float g_scratch[SCRATCH_TOTAL];

// ---------------- math helpers ----------------
__device__ __forceinline__ float sigm_f(float x) { return 1.0f / (1.0f + __expf(-x)); }
__device__ __forceinline__ float tanh_f(float x) {
    float ax = fabsf(x);
    float t  = __expf(-2.0f * ax);
    float r  = __fdividef(1.0f - t, 1.0f + t);
    return copysignf(r, x);
}

// ---------------- PTX helpers ----------------
__device__ __forceinline__ uint32_t smem_u32(const void* p) {
    uint32_t a;
    asm("{ .reg .u64 t; cvta.to.shared.u64 t, %1; cvt.u32.u64 %0, t; }" : "=r"(a) : "l"(p));
    return a;
}
__device__ __forceinline__ void cp16(uint32_t s, const void* g) {
    asm volatile("cp.async.cg.shared.global [%0], [%1], 16;" :: "r"(s), "l"(g) : "memory");
}
__device__ __forceinline__ void ldm_x4(uint32_t& r0, uint32_t& r1, uint32_t& r2, uint32_t& r3,
                                       uint32_t addr) {
    asm volatile("ldmatrix.sync.aligned.m8n8.x4.shared.b16 {%0,%1,%2,%3}, [%4];"
                 : "=r"(r0), "=r"(r1), "=r"(r2), "=r"(r3) : "r"(addr));
}
__device__ __forceinline__ void mma16816(float* c, const uint32_t* a, uint32_t b0, uint32_t b1) {
    asm volatile("mma.sync.aligned.m16n8k16.row.col.f32.f16.f16.f32 "
                 "{%0,%1,%2,%3}, {%4,%5,%6,%7}, {%8,%9}, {%0,%1,%2,%3};"
                 : "+f"(c[0]), "+f"(c[1]), "+f"(c[2]), "+f"(c[3])
                 : "r"(a[0]), "r"(a[1]), "r"(a[2]), "r"(a[3]), "r"(b0), "r"(b1));
}

static constexpr int AB_STRIDE = 10240;   // 128 rows * 80 B

// ---------------- fp16 tensor-core GEMM: C[M,N] (fp16) = A @ W^T (+f32 bias) ----------------
__global__ void __launch_bounds__(256, 2) k_gemm_mma(
    const __half* __restrict__ A1, const __half* __restrict__ W1,
    const float* __restrict__ bias, __half* __restrict__ C, int N)
{
    __shared__ __half As[2][128][40];
    __shared__ __half Bs[2][128][40];
    const int tid  = threadIdx.x;
    const int wid  = tid >> 5, lane = tid & 31;
    const int wm   = wid & 3;
    const int wn   = wid >> 2;
    const size_t bm = (size_t)blockIdx.x * 128;
    const size_t bn = (size_t)blockIdx.y * 128;

    const uint32_t sA = smem_u32(As);
    const uint32_t sB = smem_u32(Bs);

    float acc[2][8][4];
#pragma unroll
    for (int i = 0; i < 2; i++)
#pragma unroll
        for (int j = 0; j < 8; j++)
#pragma unroll
            for (int q = 0; q < 4; q++) acc[i][j][q] = 0.0f;

    const int lrow = tid >> 2;
    const int lcol = (tid & 3) << 4;
    const char* aG = (const char*)A1 + (bm + lrow) * 1024 + lcol;
    const char* bG = (const char*)W1 + (bn + lrow) * 1024 + lcol;
    const uint32_t dA = sA + lrow * 80 + lcol;
    const uint32_t dB = sB + lrow * 80 + lcol;

#define LOAD_TILE(kt, buf)                                                \
    {                                                                     \
        int ko_ = (kt) * 64;                                              \
        cp16(dA + (buf) * AB_STRIDE,           aG + ko_);                 \
        cp16(dA + (buf) * AB_STRIDE + 64 * 80, aG + 64 * 1024 + ko_);     \
        cp16(dB + (buf) * AB_STRIDE,           bG + ko_);                 \
        cp16(dB + (buf) * AB_STRIDE + 64 * 80, bG + 64 * 1024 + ko_);     \
        asm volatile("cp.async.commit_group;" ::: "memory");              \
    }

    LOAD_TILE(0, 0);

    const uint32_t mA0 = sA + (wm * 32 + (lane & 15)) * 80 + ((lane >> 4) << 4);
    const uint32_t mB0 = sB + (wn * 64 + (lane & 15)) * 80 + ((lane >> 4) << 4);

    for (int kt = 0; kt < 16; kt++) {
        int buf = kt & 1;
        if (kt < 15) {
            LOAD_TILE(kt + 1, buf ^ 1);
            asm volatile("cp.async.wait_group 1;" ::: "memory");
        } else {
            asm volatile("cp.async.wait_group 0;" ::: "memory");
        }
        __syncthreads();

#pragma unroll
        for (int ks = 0; ks < 2; ks++) {
            uint32_t a[2][4], b[4][4];
#pragma unroll
            for (int mf = 0; mf < 2; mf++)
                ldm_x4(a[mf][0], a[mf][1], a[mf][2], a[mf][3],
                       mA0 + buf * AB_STRIDE + mf * 16 * 80 + ks * 32);
#pragma unroll
            for (int nb = 0; nb < 4; nb++)
                ldm_x4(b[nb][0], b[nb][1], b[nb][2], b[nb][3],
                       mB0 + buf * AB_STRIDE + nb * 16 * 80 + ks * 32);
#pragma unroll
            for (int mf = 0; mf < 2; mf++)
#pragma unroll
                for (int nb = 0; nb < 4; nb++) {
                    mma16816(acc[mf][2 * nb + 0], a[mf], b[nb][0], b[nb][2]);
                    mma16816(acc[mf][2 * nb + 1], a[mf], b[nb][1], b[nb][3]);
                }
        }
        __syncthreads();
    }
#undef LOAD_TILE

#pragma unroll
    for (int mf = 0; mf < 2; mf++) {
#pragma unroll
        for (int nf = 0; nf < 8; nf++) {
            size_t r0 = bm + wm * 32 + mf * 16 + (lane >> 2);
            int    c0 = (int)bn + wn * 64 + nf * 8 + (lane & 3) * 2;
            float bv0 = 0.f, bv1 = 0.f;
            if (bias) { bv0 = bias[c0]; bv1 = bias[c0 + 1]; }
            *reinterpret_cast<__half2*>(&C[r0 * (size_t)N + c0]) =
                __floats2half2_rn(acc[mf][nf][0] + bv0, acc[mf][nf][1] + bv1);
            *reinterpret_cast<__half2*>(&C[(r0 + 8) * (size_t)N + c0]) =
                __floats2half2_rn(acc[mf][nf][2] + bv0, acc[mf][nf][3] + bv1);
        }
    }
}

// ---------------- one-shot cast of all weights + decoder input ----------------
static constexpr size_t CN0 = (size_t)Gd * Hd;          // enc_whh
static constexpr size_t CN1 = CN0 + (size_t)Gd * Hd;    // dec_whh
static constexpr size_t CN2 = CN1 + (size_t)Gd * Hd;    // dec_wih
static constexpr size_t CN3 = CN2 + (size_t)Hd * Hd;    // w3
static constexpr size_t CN4 = CN3 + (size_t)Hd * Hd;    // w4
static constexpr size_t CN5 = CN4 + (size_t)Bz * Hd;    // dec_in

__global__ void k_cast_all(const float* __restrict__ a0, const float* __restrict__ a1,
                           const float* __restrict__ a2, const float* __restrict__ a3,
                           const float* __restrict__ a4, const float* __restrict__ a5,
                           __half* __restrict__ b0, __half* __restrict__ b1,
                           __half* __restrict__ b2, __half* __restrict__ b3,
                           __half* __restrict__ b4, __half* __restrict__ b5)
{
    size_t idx = (size_t)blockIdx.x * blockDim.x + threadIdx.x;
    if      (idx < CN0) b0[idx]       = __float2half(a0[idx]);
    else if (idx < CN1) b1[idx - CN0] = __float2half(a1[idx - CN0]);
    else if (idx < CN2) b2[idx - CN1] = __float2half(a2[idx - CN1]);
    else if (idx < CN3) b3[idx - CN2] = __float2half(a3[idx - CN2]);
    else if (idx < CN4) b4[idx - CN3] = __float2half(a4[idx - CN3]);
    else if (idx < CN5) b5[idx - CN4] = __float2half(a5[idx - CN4]);
}

// ---------------- combine: cw = enc_wih @ emb_w, cb = enc_wih@emb_b + enc_bih ----------------
__global__ void k_combine(const float* __restrict__ enc_wih, const float* __restrict__ emb_w,
                          const float* __restrict__ emb_b,  const float* __restrict__ enc_bih,
                          float* __restrict__ cw, float* __restrict__ cb)
{
    int g = blockIdx.x, tid = threadIdx.x;
    float p[IND + 1];
#pragma unroll
    for (int i = 0; i <= IND; i++) p[i] = 0.0f;
    const float* wr = enc_wih + (size_t)g * Hd;
    for (int k = tid; k < Hd; k += 128) {
        float wv = wr[k];
#pragma unroll
        for (int i = 0; i < IND; i++) p[i] += wv * emb_w[(size_t)k * IND + i];
        p[IND] += wv * emb_b[k];
    }
#pragma unroll
    for (int i = 0; i <= IND; i++)
        for (int o = 16; o; o >>= 1) p[i] += __shfl_xor_sync(0xffffffffu, p[i], o);
    __shared__ float red[IND + 1][4];
    int wid = tid >> 5, lane = tid & 31;
    if (!lane)
#pragma unroll
        for (int i = 0; i <= IND; i++) red[i][wid] = p[i];
    __syncthreads();
    if (tid <= IND) {
        float s = red[tid][0] + red[tid][1] + red[tid][2] + red[tid][3];
        if (tid < IND) cw[(size_t)g * IND + tid] = s;
        else           cb[g] = s + enc_bih[g];
    }
}

// ---------------- XG_ENC precompute: xg[t][b][g] = items[b,t,:].cw[g,:] + cb[g] (fp16) ----------------
// Block: 64 bl-rows x 512 g-cols. cw pair per thread in registers; items rows broadcast via smem.
__global__ void __launch_bounds__(256) k_xg_enc(
    const float* __restrict__ items, const float* __restrict__ cw,
    const float* __restrict__ cb, __half* __restrict__ xg)
{
    __shared__ float its[64][IND];
    const int tid = threadIdx.x;
    const int bl0 = blockIdx.x * 64;
    const int gp  = blockIdx.y * 512 + tid * 2;

    for (int i = tid; i < 64 * IND; i += 256)
        its[i >> 3][i & 7] = items[(size_t)(bl0 + (i >> 3)) * IND + (i & 7)];

    const float4* wv = reinterpret_cast<const float4*>(cw + (size_t)gp * IND);
    float4 a0 = wv[0], a1 = wv[1], b0 = wv[2], b1 = wv[3];
    float c0 = cb[gp], c1 = cb[gp + 1];
    __syncthreads();

#pragma unroll 4
    for (int r = 0; r < 64; r++) {
        int bl = bl0 + r;
        int b = bl / Ls, t = bl - b * Ls;
        const float* it = its[r];
        float i0 = it[0], i1 = it[1], i2 = it[2], i3 = it[3];
        float i4 = it[4], i5 = it[5], i6 = it[6], i7 = it[7];
        float x0 = c0 + i0 * a0.x + i1 * a0.y + i2 * a0.z + i3 * a0.w
                      + i4 * a1.x + i5 * a1.y + i6 * a1.z + i7 * a1.w;
        float x1 = c1 + i0 * b0.x + i1 * b0.y + i2 * b0.z + i3 * b0.w
                      + i4 * b1.x + i5 * b1.y + i6 * b1.z + i7 * b1.w;
        *reinterpret_cast<__half2*>(&xg[((size_t)t * Bz + b) * Gd + gp]) =
            __floats2half2_rn(x0, x1);
    }
}

// ---------------- unified GRU gate (fp16 xg/hg/hprev; hg/hprev nullable) ----------------
__global__ void k_gate(const __half2* __restrict__ xg, const __half2* __restrict__ hg,
                       const float* __restrict__ bhh,
                       const __half2* __restrict__ hprev, __half2* __restrict__ h1)
{
    int idx = blockIdx.x * blockDim.x + threadIdx.x;   // Bz * 256
    int b = idx >> 8, q = idx & 255;
    const __half2* x = xg + (size_t)b * 768;
    float2 xr = __half22float2(x[q]);
    float2 xz = __half22float2(x[256 + q]);
    float2 xn = __half22float2(x[512 + q]);
    float hr0, hr1, hz0, hz1, hn0, hn1;
    if (hg) {
        const __half2* g = hg + (size_t)b * 768;
        float2 v;
        v = __half22float2(g[q]);       hr0 = v.x; hr1 = v.y;
        v = __half22float2(g[256 + q]); hz0 = v.x; hz1 = v.y;
        v = __half22float2(g[512 + q]); hn0 = v.x; hn1 = v.y;
    } else {
        int j0 = q * 2;
        hr0 = bhh[j0];          hr1 = bhh[j0 + 1];
        hz0 = bhh[Hd + j0];     hz1 = bhh[Hd + j0 + 1];
        hn0 = bhh[2 * Hd + j0]; hn1 = bhh[2 * Hd + j0 + 1];
    }
    float hp0 = 0.f, hp1 = 0.f;
    if (hprev) {
        float2 v = __half22float2(hprev[(size_t)b * 256 + q]);
        hp0 = v.x; hp1 = v.y;
    }
    float r0 = sigm_f(xr.x + hr0), r1 = sigm_f(xr.y + hr1);
    float z0 = sigm_f(xz.x + hz0), z1 = sigm_f(xz.y + hz1);
    float n0 = tanh_f(xn.x + r0 * hn0), n1 = tanh_f(xn.y + r1 * hn1);
    h1[(size_t)b * 256 + q] =
        __floats2half2_rn(n0 + z0 * (hp0 - n0), n1 + z1 * (hp1 - n1));
}

// ---------------- batched out_seq over all (t, l): one block per b ----------------
__global__ void __launch_bounds__(256) k_seq_all(
    const __half* __restrict__ encw3, const __half* __restrict__ A_all,
    const float* __restrict__ v2, float* __restrict__ out)
{
    int b = blockIdx.x, tid = threadIdx.x;
    int wid = tid >> 5, lane = tid & 31;
    __shared__ float Ash[Ls][Hd];
    __shared__ float v2s[Hd];
    __shared__ float red[8][Ls];
    for (int i = tid; i < Hd; i += 256) v2s[i] = v2[i];
    for (int t = 0; t < Ls; t++)
        for (int i = tid; i < Hd; i += 256)
            Ash[t][i] = __half2float(A_all[((size_t)t * Bz + b) * Hd + i]);
    __syncthreads();

    for (int l = 0; l < Ls; l++) {
        const __half* e = encw3 + ((size_t)l * Bz + b) * Hd;
        float s[Ls];
#pragma unroll
        for (int t = 0; t < Ls; t++) s[t] = 0.0f;
#pragma unroll
        for (int it = 0; it < 2; it++) {
            int k = tid + it * 256;
            float ek = __half2float(e[k]), vk = v2s[k];
#pragma unroll
            for (int t = 0; t < Ls; t++) s[t] += vk * tanh_f(ek + Ash[t][k]);
        }
#pragma unroll
        for (int t = 0; t < Ls; t++)
            for (int o = 16; o; o >>= 1) s[t] += __shfl_xor_sync(0xffffffffu, s[t], o);
        if (!lane)
#pragma unroll
            for (int t = 0; t < Ls; t++) red[wid][t] = s[t];
        __syncthreads();
        if (tid < Ls) {
            float tot = 0.0f;
#pragma unroll
            for (int w = 0; w < 8; w++) tot += red[w][tid];
            out[((size_t)b * Ls + tid) * Ls + l] = tot;
        }
        __syncthreads();
    }
}

// ---------------- batched out_ori: one warp per (t, b), fp16 h ----------------
__global__ void k_ori_all(const __half* __restrict__ H1_all, const float* __restrict__ wori,
                          const float* __restrict__ bori, float* __restrict__ out)
{
    int gw   = (blockIdx.x * blockDim.x + threadIdx.x) >> 5;  // t*Bz + b
    int lane = threadIdx.x & 31;
    int t = gw >> 12, b = gw & 4095;
    float s[6] = {0, 0, 0, 0, 0, 0};
    const __half* hb = H1_all + ((size_t)t * Bz + b) * Hd;
    for (int k = lane; k < Hd; k += 32) {
        float hv = __half2float(hb[k]);
#pragma unroll
        for (int j = 0; j < 6; j++) s[j] += hv * wori[(size_t)j * Gd + Hd + k];
    }
#pragma unroll
    for (int j = 0; j < 6; j++)
        for (int o = 16; o; o >>= 1) s[j] += __shfl_xor_sync(0xffffffffu, s[j], o);
    if (!lane)
#pragma unroll
        for (int j = 0; j < 6; j++)
            out[((size_t)b * Ls + t) * 6 + j] = s[j] + bori[j];
}

// ---------------- launch ----------------
extern "C" void kernel_launch(void* const* d_in, const int* in_sizes, int n_in,
                              void* d_out, int out_size)
{
    const float* items    = (const float*)d_in[0];
    const float* dec_in   = (const float*)d_in[1];
    const float* emb_w    = (const float*)d_in[2];
    const float* emb_b    = (const float*)d_in[3];
    const float* enc_wih  = (const float*)d_in[4];
    const float* enc_whh  = (const float*)d_in[5];
    const float* enc_bih  = (const float*)d_in[6];
    const float* enc_bhh  = (const float*)d_in[7];
    const float* dec_wih  = (const float*)d_in[8];
    const float* dec_whh  = (const float*)d_in[9];
    const float* dec_bih  = (const float*)d_in[10];
    const float* dec_bhh  = (const float*)d_in[11];
    const float* w3       = (const float*)d_in[14];
    const float* w4       = (const float*)d_in[15];
    const float* v2       = (const float*)d_in[20];
    const float* wori     = (const float*)d_in[23];
    const float* bori     = (const float*)d_in[24];

    float* out_seq = (float*)d_out;                        // (Bz, Ls, Ls)
    float* out_ori = (float*)d_out + (size_t)Bz * Ls * Ls; // (Bz, Ls, 6)

    float* S = nullptr;
    cudaGetSymbolAddress((void**)&S, g_scratch);
    float* CW      = S + OFF_CW;
    float* CB      = S + OFF_CB;
    __half* XG_DEC = (__half*)(S + OFF_XG_DEC);
    __half* HG     = (__half*)(S + OFF_HG);
    __half* XG_ENC = (__half*)(S + OFF_XG_ENC);
    __half* ENC1   = (__half*)(S + OFF_ENC1);
    __half* ENC_W3 = (__half*)(S + OFF_ENC_W3);
    __half* H1_ALL = (__half*)(S + OFF_H1_ALL);
    __half* A_ALL  = (__half*)(S + OFF_A_ALL);
    __half* DEC1   = (__half*)(S + OFF_DEC1);
    __half* WHHE1  = (__half*)(S + OFF_WHHE1);
    __half* WHHD1  = (__half*)(S + OFF_WHHD1);
    __half* WIHD1  = (__half*)(S + OFF_WIHD1);
    __half* W31    = (__half*)(S + OFF_W31);
    __half* W41    = (__half*)(S + OFF_W41);

    // prologue: casts, combined enc-input weights, XG_ENC precompute
    k_cast_all<<<(unsigned)(CN5 / 256), 256>>>(enc_whh, dec_whh, dec_wih, w3, w4, dec_in,
                                               WHHE1, WHHD1, WIHD1, W31, W41, DEC1);
    k_combine<<<Gd, 128>>>(enc_wih, emb_w, emb_b, enc_bih, CW, CB);
    k_xg_enc<<<dim3(Bz * Ls / 64, Gd / 512), 256>>>(items, CW, CB, XG_ENC);

    // decoder input gates (step-invariant)
    k_gemm_mma<<<dim3(Bz / 128, Gd / 128), 256>>>(DEC1, WIHD1, dec_bih, XG_DEC, Gd);

    // encoder GRU scan
    for (int t = 0; t < Ls; t++) {
        const __half2* xt  = (const __half2*)(XG_ENC + (size_t)t * Bz * Gd);
        const __half2* hp1 = t ? (const __half2*)(ENC1 + (size_t)(t - 1) * Bz * Hd) : nullptr;
        if (t)
            k_gemm_mma<<<dim3(Bz / 128, Gd / 128), 256>>>(
                ENC1 + (size_t)(t - 1) * Bz * Hd, WHHE1, enc_bhh, HG, Gd);
        k_gate<<<Bz, 256>>>(xt, t ? (const __half2*)HG : nullptr, enc_bhh, hp1,
                            (__half2*)(ENC1 + (size_t)t * Bz * Hd));
    }

    // enc_w3 = enc_out @ w3^T  (all Ls*Bz rows batched)
    k_gemm_mma<<<dim3((Ls * Bz) / 128, Hd / 128), 256>>>(ENC1, W31, nullptr, ENC_W3, Hd);

    // decoder scan (w4 GEMM batched after)
    const __half* hp1 = ENC1 + (size_t)(Ls - 1) * Bz * Hd;
    for (int t = 0; t < Ls; t++) {
        __half* ht1 = H1_ALL + (size_t)t * Bz * Hd;
        k_gemm_mma<<<dim3(Bz / 128, Gd / 128), 256>>>(hp1, WHHD1, dec_bhh, HG, Gd);
        k_gate<<<Bz, 256>>>((const __half2*)XG_DEC, (const __half2*)HG, dec_bhh,
                            (const __half2*)hp1, (__half2*)ht1);
        hp1 = ht1;
    }

    // A_ALL = H1_ALL @ w4^T  (all Ls*Bz rows batched)
    k_gemm_mma<<<dim3((Ls * Bz) / 128, Hd / 128), 256>>>(H1_ALL, W41, nullptr, A_ALL, Hd);

    // batched epilogues
    k_seq_all<<<Bz, 256>>>(ENC_W3, A_ALL, v2, out_seq);
    k_ori_all<<<(Bz * Ls) / 8, 256>>>(H1_ALL, wori, bori, out_ori);
}